// round 1
// baseline (speedup 1.0000x reference)
#include <cuda_runtime.h>
#include <math.h>

// ---- problem constants ----
#define Lx   12
#define Dd   726
#define Hh   16
#define HDd  45
#define Tt   258
#define Vv   50257
#define Bbt  16
#define FFf  2904           // 4*D
#define NT   (Bbt*Tt)       // 4128 tokens
#define HHd  (Hh*HDd)       // 720

// ---- scratch (__device__ globals; no allocation allowed) ----
__device__ float g_x [NT*Dd];
__device__ float g_h [NT*Dd];
__device__ float g_q [NT*HHd];
__device__ float g_k [NT*HHd];
__device__ float g_v [NT*HHd];
__device__ float g_o [NT*HHd];
__device__ float g_ff[NT*FFf];
__device__ float g_wq[Lx*Dd*HHd];
__device__ float g_wk[Lx*Dd*HHd];
__device__ float g_wv[Lx*Dd*HHd];

// ---- repack (L,H,D,HD) -> (L, D, H*HD) ----
__global__ void repack_k(const float* __restrict__ src, float* __restrict__ dst) {
    int i = blockIdx.x * blockDim.x + threadIdx.x;
    const int total = Lx * Dd * HHd;
    if (i >= total) return;
    int n    = i % HHd;
    int rest = i / HHd;
    int d    = rest % Dd;
    int l    = rest / Dd;
    int h  = n / HDd;
    int kk = n % HDd;
    dst[i] = src[((l * Hh + h) * Dd + d) * HDd + kk];
}

// ---- embedding: x = tok_emb[idx] + pos_emb ----
__global__ void embed_k(const int* __restrict__ idx,
                        const float* __restrict__ tok,
                        const float* __restrict__ pos) {
    int i = blockIdx.x * blockDim.x + threadIdx.x;
    if (i >= NT * Dd) return;
    int d = i % Dd;
    int n = i / Dd;
    int t = n % Tt;
    g_x[i] = tok[idx[n] * Dd + d] + pos[t * Dd + d];
}

// ---- layernorm (block per row) ----
__global__ void lnorm_k(const float* __restrict__ in, float* __restrict__ out,
                        const float* __restrict__ g, const float* __restrict__ b) {
    int row = blockIdx.x;
    const float* xr = in + (size_t)row * Dd;
    __shared__ float r1[256];
    __shared__ float r2[256];
    float s = 0.f, ss = 0.f;
    for (int d = threadIdx.x; d < Dd; d += 256) {
        float v = xr[d];
        s += v; ss += v * v;
    }
    r1[threadIdx.x] = s; r2[threadIdx.x] = ss;
    __syncthreads();
    for (int o = 128; o > 0; o >>= 1) {
        if (threadIdx.x < o) { r1[threadIdx.x] += r1[threadIdx.x + o]; r2[threadIdx.x] += r2[threadIdx.x + o]; }
        __syncthreads();
    }
    float mean = r1[0] / Dd;
    float var  = r2[0] / Dd - mean * mean;
    float inv  = rsqrtf(var + 1e-5f);
    for (int d = threadIdx.x; d < Dd; d += 256) {
        out[(size_t)row * Dd + d] = (xr[d] - mean) * inv * g[d] + b[d];
    }
}

// ---- generic tiled SGEMM: C[m,n] = sum_k A[m,k]*B[k,n] (+bias)(+resid)(relu) ----
#define F_BIAS  1
#define F_RELU  2
#define F_RESID 4
#define BM 64
#define BN 64
#define BK 16

__global__ void sgemm_k(const float* __restrict__ A, const float* __restrict__ Bm,
                        const float* __restrict__ bias, const float* __restrict__ resid,
                        float* __restrict__ C,
                        int M, int N, int K, int lda, int ldb, int ldc, int flags) {
    __shared__ float As[BK][BM];
    __shared__ float Bs[BK][BN];
    int tid = threadIdx.x;              // 256 threads
    int tx = tid & 15, ty = tid >> 4;
    int m0 = blockIdx.y * BM, n0 = blockIdx.x * BN;

    float acc[4][4];
    #pragma unroll
    for (int i = 0; i < 4; i++)
        #pragma unroll
        for (int j = 0; j < 4; j++) acc[i][j] = 0.f;

    const int la_m = tid >> 2;          // 0..63
    const int la_k = (tid & 3) * 4;     // 0,4,8,12
    const int lb_k = tid >> 4;          // 0..15
    const int lb_n = (tid & 15) * 4;    // 0..60

    for (int k0 = 0; k0 < K; k0 += BK) {
        int am = m0 + la_m;
        #pragma unroll
        for (int i = 0; i < 4; i++) {
            int ak = k0 + la_k + i;
            As[la_k + i][la_m] = (am < M && ak < K) ? A[(size_t)am * lda + ak] : 0.f;
        }
        int bk = k0 + lb_k;
        #pragma unroll
        for (int j = 0; j < 4; j++) {
            int bn = n0 + lb_n + j;
            Bs[lb_k][lb_n + j] = (bk < K && bn < N) ? Bm[(size_t)bk * ldb + bn] : 0.f;
        }
        __syncthreads();
        #pragma unroll
        for (int kk = 0; kk < BK; kk++) {
            float a[4], bv[4];
            #pragma unroll
            for (int i = 0; i < 4; i++) a[i]  = As[kk][ty * 4 + i];
            #pragma unroll
            for (int j = 0; j < 4; j++) bv[j] = Bs[kk][tx * 4 + j];
            #pragma unroll
            for (int i = 0; i < 4; i++)
                #pragma unroll
                for (int j = 0; j < 4; j++) acc[i][j] += a[i] * bv[j];
        }
        __syncthreads();
    }

    #pragma unroll
    for (int i = 0; i < 4; i++) {
        int m = m0 + ty * 4 + i;
        if (m >= M) continue;
        #pragma unroll
        for (int j = 0; j < 4; j++) {
            int n = n0 + tx * 4 + j;
            if (n >= N) continue;
            float v = acc[i][j];
            if (flags & F_BIAS)  v += bias[n];
            if (flags & F_RESID) v += resid[(size_t)m * ldc + n];
            if (flags & F_RELU)  v = fmaxf(v, 0.f);
            C[(size_t)m * ldc + n] = v;
        }
    }
}

// ---- fused attention: scores + causal softmax + AV, one block per (b,h,t) ----
__global__ void attn_k(const float* __restrict__ q, const float* __restrict__ kb,
                       const float* __restrict__ vb, float* __restrict__ ob) {
    int t = blockIdx.x, h = blockIdx.y, b = blockIdx.z;
    int tid = threadIdx.x;      // 256
    __shared__ float qr[HDd];
    __shared__ float att[Tt];
    __shared__ float red[256];

    const size_t base = (size_t)(b * Tt) * HHd + h * HDd;   // row stride = HHd
    if (tid < HDd) qr[tid] = q[base + (size_t)t * HHd + tid];
    __syncthreads();

    const float scale = 1.0f / sqrtf((float)HDd);
    for (int s = tid; s < Tt; s += 256) {
        float dot = -1e30f;
        if (s <= t) {
            dot = 0.f;
            const float* kr = kb + base + (size_t)s * HHd;
            #pragma unroll
            for (int d = 0; d < HDd; d++) dot += qr[d] * kr[d];
            dot *= scale;
        }
        att[s] = dot;
    }
    __syncthreads();

    // max reduce
    float mx = -1e30f;
    for (int s = tid; s < Tt; s += 256) mx = fmaxf(mx, att[s]);
    red[tid] = mx; __syncthreads();
    for (int o = 128; o > 0; o >>= 1) {
        if (tid < o) red[tid] = fmaxf(red[tid], red[tid + o]);
        __syncthreads();
    }
    mx = red[0];
    __syncthreads();

    // exp + sum
    float sum = 0.f;
    for (int s = tid; s < Tt; s += 256) {
        float e = __expf(att[s] - mx);
        att[s] = e; sum += e;
    }
    red[tid] = sum; __syncthreads();
    for (int o = 128; o > 0; o >>= 1) {
        if (tid < o) red[tid] += red[tid + o];
        __syncthreads();
    }
    float inv = 1.f / red[0];
    __syncthreads();

    // AV
    for (int d = tid; d < HDd; d += 256) {
        float accv = 0.f;
        for (int s = 0; s <= t; s++) accv += att[s] * vb[base + (size_t)s * HHd + d];
        ob[base + (size_t)t * HHd + d] = accv * inv;
    }
}

// ---- host orchestration ----
static float* sym_addr(const void* sym) {
    void* p = nullptr;
    cudaGetSymbolAddress(&p, sym);
    return (float*)p;
}

extern "C" void kernel_launch(void* const* d_in, const int* in_sizes, int n_in,
                              void* d_out, int out_size) {
    const int*   idx     = (const int*)  d_in[0];
    const float* tok_emb = (const float*)d_in[1];
    const float* pos_emb = (const float*)d_in[2];
    const float* Wq      = (const float*)d_in[3];
    const float* Wk      = (const float*)d_in[4];
    const float* Wv      = (const float*)d_in[5];
    const float* Wproj   = (const float*)d_in[6];
    const float* bproj   = (const float*)d_in[7];
    const float* ln1_g   = (const float*)d_in[8];
    const float* ln1_b   = (const float*)d_in[9];
    const float* ln2_g   = (const float*)d_in[10];
    const float* ln2_b   = (const float*)d_in[11];
    const float* W1      = (const float*)d_in[12];
    const float* b1      = (const float*)d_in[13];
    const float* W2      = (const float*)d_in[14];
    const float* b2      = (const float*)d_in[15];
    const float* lnf_g   = (const float*)d_in[16];
    const float* lnf_b   = (const float*)d_in[17];
    const float* Wlm     = (const float*)d_in[18];
    const float* blm     = (const float*)d_in[19];
    float* out = (float*)d_out;

    float* px  = sym_addr(g_x);
    float* ph  = sym_addr(g_h);
    float* pq  = sym_addr(g_q);
    float* pk  = sym_addr(g_k);
    float* pv  = sym_addr(g_v);
    float* po  = sym_addr(g_o);
    float* pff = sym_addr(g_ff);
    float* pwq = sym_addr(g_wq);
    float* pwk = sym_addr(g_wk);
    float* pwv = sym_addr(g_wv);

    // repack QKV weights into [L, D, H*HD]
    {
        const int total = Lx * Dd * HHd;
        int nb = (total + 255) / 256;
        repack_k<<<nb, 256>>>(Wq, pwq);
        repack_k<<<nb, 256>>>(Wk, pwk);
        repack_k<<<nb, 256>>>(Wv, pwv);
    }

    // embedding
    {
        const int total = NT * Dd;
        embed_k<<<(total + 255) / 256, 256>>>(idx, tok_emb, pos_emb);
    }

    dim3 gQKV((HHd + BN - 1) / BN, (NT + BM - 1) / BM);
    dim3 gPRJ((Dd  + BN - 1) / BN, (NT + BM - 1) / BM);
    dim3 gFF1((FFf + BN - 1) / BN, (NT + BM - 1) / BM);
    dim3 gFF2((Dd  + BN - 1) / BN, (NT + BM - 1) / BM);
    dim3 gLM ((Vv  + BN - 1) / BN, (NT + BM - 1) / BM);
    dim3 gATT(Tt, Hh, Bbt);

    for (int l = 0; l < Lx; l++) {
        // h = LN1(x)
        lnorm_k<<<NT, 256>>>(px, ph, ln1_g + l * Dd, ln1_b + l * Dd);
        // q,k,v = h @ Wqkv  -> [NT, H*HD]
        sgemm_k<<<gQKV, 256>>>(ph, pwq + (size_t)l * Dd * HHd, nullptr, nullptr, pq,
                               NT, HHd, Dd, Dd, HHd, HHd, 0);
        sgemm_k<<<gQKV, 256>>>(ph, pwk + (size_t)l * Dd * HHd, nullptr, nullptr, pk,
                               NT, HHd, Dd, Dd, HHd, HHd, 0);
        sgemm_k<<<gQKV, 256>>>(ph, pwv + (size_t)l * Dd * HHd, nullptr, nullptr, pv,
                               NT, HHd, Dd, Dd, HHd, HHd, 0);
        // attention
        attn_k<<<gATT, 256>>>(pq, pk, pv, po);
        // x = x + o @ Wproj + bproj
        sgemm_k<<<gPRJ, 256>>>(po, Wproj + (size_t)l * HHd * Dd, bproj + l * Dd, px, px,
                               NT, Dd, HHd, HHd, Dd, Dd, F_BIAS | F_RESID);
        // h = LN2(x)
        lnorm_k<<<NT, 256>>>(px, ph, ln2_g + l * Dd, ln2_b + l * Dd);
        // ff = relu(h @ W1 + b1)
        sgemm_k<<<gFF1, 256>>>(ph, W1 + (size_t)l * Dd * FFf, b1 + (size_t)l * FFf, nullptr, pff,
                               NT, FFf, Dd, Dd, FFf, FFf, F_BIAS | F_RELU);
        // x = x + ff @ W2 + b2
        sgemm_k<<<gFF2, 256>>>(pff, W2 + (size_t)l * FFf * Dd, b2 + l * Dd, px, px,
                               NT, Dd, FFf, FFf, Dd, Dd, F_BIAS | F_RESID);
    }

    // final LN + LM head
    lnorm_k<<<NT, 256>>>(px, ph, lnf_g, lnf_b);
    sgemm_k<<<gLM, 256>>>(ph, Wlm, blm, nullptr, out,
                          NT, Vv, Dd, Dd, Vv, Vv, F_BIAS);
}

// round 4
// speedup vs baseline: 1.7651x; 1.7651x over previous
#include <cuda_runtime.h>
#include <cuda_bf16.h>
#include <stdint.h>
#include <math.h>

// ---- problem constants ----
#define Lx   12
#define Dd   726
#define Hh   16
#define HDd  45
#define Tt   258
#define Vv   50257
#define Bbt  16
#define FFf  2904           // 4*D
#define NT   (Bbt*Tt)       // 4128 tokens
#define HHd  (Hh*HDd)       // 720
#define QKVW (3*HHd)        // 2160

#define F_BIAS  1
#define F_RELU  2
#define F_RESID 4

// ---- scratch (__device__ globals; no allocation allowed) ----
__device__ float g_x   [NT*Dd];
__device__ float g_h   [NT*Dd];
__device__ float g_qkv [NT*QKVW];
__device__ float g_o   [NT*HHd];
__device__ float g_ff  [NT*FFf];
__device__ float g_wqkv[Lx*Dd*QKVW];

// =====================================================================
// helpers
// =====================================================================
__device__ __forceinline__ uint32_t smem_u32(const void* p) {
    uint32_t a;
    asm("{ .reg .u64 t; cvta.to.shared.u64 t, %1; cvt.u32.u64 %0, t; }"
        : "=r"(a) : "l"(p));
    return a;
}
__device__ __forceinline__ void ldsm4(uint32_t& r0, uint32_t& r1,
                                      uint32_t& r2, uint32_t& r3, uint32_t addr) {
    asm volatile("ldmatrix.sync.aligned.m8n8.x4.shared.b16 {%0,%1,%2,%3}, [%4];"
                 : "=r"(r0), "=r"(r1), "=r"(r2), "=r"(r3) : "r"(addr));
}
__device__ __forceinline__ void mma16816(float* c, const uint32_t* a,
                                         uint32_t b0, uint32_t b1) {
    asm volatile(
        "mma.sync.aligned.m16n8k16.row.col.f32.bf16.bf16.f32 "
        "{%0,%1,%2,%3},{%4,%5,%6,%7},{%8,%9},{%0,%1,%2,%3};"
        : "+f"(c[0]), "+f"(c[1]), "+f"(c[2]), "+f"(c[3])
        : "r"(a[0]), "r"(a[1]), "r"(a[2]), "r"(a[3]), "r"(b0), "r"(b1));
}

// =====================================================================
// HMMA bf16 split-precision GEMM: C[M,N] = A[M,K] @ B[K,N]
// CTA tile 128x128, K-chunk 32, 8 warps (4m x 2n), warp tile 32x64.
// =====================================================================
#define BKP 40                      // padded K row (elements) -> 80B stride
#define ABUF 5120                   // 128*40 elements per (hi|lo) plane
#define BUFSZ 20480                 // elements per buffer (Ahi,Alo,Bhi,Blo)

__global__ __launch_bounds__(256) void hgemm_k(
    const float* __restrict__ A, const float* __restrict__ B,
    const float* __restrict__ bias, const float* __restrict__ resid,
    float* __restrict__ C,
    int M, int N, int K, int lda, int ldb, int ldc, int flags)
{
    extern __shared__ __align__(1024) char smraw[];
    __nv_bfloat16* sb = (__nv_bfloat16*)smraw;
    const uint32_t sbase = smem_u32(sb);

    const int tid  = threadIdx.x;
    const int wid  = tid >> 5;
    const int lane = tid & 31;
    const int warp_m = wid & 3;        // 0..3  -> 32 rows each
    const int warp_n = wid >> 2;       // 0..1  -> 64 cols each

    const int m0 = blockIdx.x << 7;
    const int n0 = blockIdx.y << 7;

    float c[2][8][4];
    #pragma unroll
    for (int i = 0; i < 2; i++)
        #pragma unroll
        for (int j = 0; j < 8; j++)
            #pragma unroll
            for (int q = 0; q < 4; q++) c[i][j][q] = 0.f;

    float aR[16], bR[16];
    const int nCh = (K + 31) >> 5;

    // ---- global -> regs for one chunk ----
    auto ldg = [&](int ch) {
        const int k0 = ch << 5;
        #pragma unroll
        for (int i = 0; i < 16; i++) {
            int idx = tid + (i << 8);
            int r = idx >> 5, k = idx & 31;
            int m = m0 + r, kk = k0 + k;
            aR[i] = (m < M && kk < K) ? A[(size_t)m * lda + kk] : 0.f;
        }
        #pragma unroll
        for (int i = 0; i < 16; i++) {
            int idx = tid + (i << 8);
            int n = idx & 127, kr = idx >> 7;
            int gn = n0 + n, kk = k0 + kr;
            bR[i] = (gn < N && kk < K) ? B[(size_t)kk * ldb + gn] : 0.f;
        }
    };
    // ---- regs -> smem (hi/lo split), buf is 0/1 parity ----
    auto sts = [&](int buf) {
        const int base = buf * BUFSZ;
        #pragma unroll
        for (int i = 0; i < 16; i++) {
            int idx = tid + (i << 8);
            int r = idx >> 5, k = idx & 31;
            float v = aR[i];
            __nv_bfloat16 h = __float2bfloat16(v);
            __nv_bfloat16 l = __float2bfloat16(v - __bfloat162float(h));
            sb[base + r * BKP + k]        = h;
            sb[base + ABUF + r * BKP + k] = l;
        }
        #pragma unroll
        for (int i = 0; i < 16; i++) {
            int idx = tid + (i << 8);
            int n = idx & 127, kr = idx >> 7;
            float v = bR[i];
            __nv_bfloat16 h = __float2bfloat16(v);
            __nv_bfloat16 l = __float2bfloat16(v - __bfloat162float(h));
            sb[base + 2 * ABUF + n * BKP + kr] = h;
            sb[base + 3 * ABUF + n * BKP + kr] = l;
        }
    };

    ldg(0);
    sts(0);
    __syncthreads();

    for (int ch = 0; ch < nCh; ch++) {
        if (ch + 1 < nCh) ldg(ch + 1);

        const uint32_t bufb = sbase + (uint32_t)(ch & 1) * BUFSZ * 2;  // bytes
        #pragma unroll
        for (int ks = 0; ks < 2; ks++) {
            // A fragments (2 m-tiles, hi+lo)
            uint32_t ahi[2][4], alo[2][4];
            const int arow = warp_m * 32 + (lane & 15);
            const int acol = ks * 16 + ((lane >> 4) << 3);
            #pragma unroll
            for (int mt = 0; mt < 2; mt++) {
                uint32_t ad = bufb + (uint32_t)(((arow + mt * 16) * BKP + acol) << 1);
                ldsm4(ahi[mt][0], ahi[mt][1], ahi[mt][2], ahi[mt][3], ad);
                ldsm4(alo[mt][0], alo[mt][1], alo[mt][2], alo[mt][3], ad + ABUF * 2);
            }
            // B fragments: per 16-n block one ldmatrix.x4 per plane
            const int brow = warp_n * 64 + ((lane >> 4) << 3) + (lane & 7);
            const int bcol = ks * 16 + (((lane >> 3) & 1) << 3);
            #pragma unroll
            for (int nt2 = 0; nt2 < 4; nt2++) {
                uint32_t bd = bufb + (uint32_t)((2 * ABUF + (brow + nt2 * 16) * BKP + bcol) << 1);
                uint32_t bh[4], bl[4];
                ldsm4(bh[0], bh[1], bh[2], bh[3], bd);
                ldsm4(bl[0], bl[1], bl[2], bl[3], bd + ABUF * 2);
                #pragma unroll
                for (int hh = 0; hh < 2; hh++) {
                    const int nt = nt2 * 2 + hh;
                    #pragma unroll
                    for (int mt = 0; mt < 2; mt++) {
                        mma16816(c[mt][nt], ahi[mt], bh[hh * 2], bh[hh * 2 + 1]);
                        mma16816(c[mt][nt], ahi[mt], bl[hh * 2], bl[hh * 2 + 1]);
                        mma16816(c[mt][nt], alo[mt], bh[hh * 2], bh[hh * 2 + 1]);
                    }
                }
            }
        }
        if (ch + 1 < nCh) sts((ch + 1) & 1);   // FIX: parity, not raw index
        __syncthreads();
    }

    // ---- epilogue: fragment regs -> global ----
    #pragma unroll
    for (int mt = 0; mt < 2; mt++) {
        #pragma unroll
        for (int nt = 0; nt < 8; nt++) {
            int rb = m0 + warp_m * 32 + mt * 16 + (lane >> 2);
            int nc = n0 + warp_n * 64 + nt * 8 + ((lane & 3) << 1);
            #pragma unroll
            for (int half = 0; half < 2; half++) {
                int m = rb + half * 8;
                if (m < M) {
                    #pragma unroll
                    for (int j = 0; j < 2; j++) {
                        int n = nc + j;
                        if (n < N) {
                            float v = c[mt][nt][half * 2 + j];
                            if (flags & F_BIAS)  v += bias[n];
                            if (flags & F_RESID) v += resid[(size_t)m * ldc + n];
                            if (flags & F_RELU)  v = fmaxf(v, 0.f);
                            C[(size_t)m * ldc + n] = v;
                        }
                    }
                }
            }
        }
    }
}

// =====================================================================
// repack (L,H,D,HD) x3 -> (L, D, 3*H*HD)
// =====================================================================
__global__ void repack_qkv_k(const float* __restrict__ Wq,
                             const float* __restrict__ Wk,
                             const float* __restrict__ Wv,
                             float* __restrict__ dst) {
    int i = blockIdx.x * blockDim.x + threadIdx.x;
    const int total = Lx * Dd * QKVW;
    if (i >= total) return;
    int j    = i % QKVW;
    int rest = i / QKVW;
    int d    = rest % Dd;
    int l    = rest / Dd;
    int sel = j / HHd;
    int n   = j % HHd;
    int h  = n / HDd;
    int kk = n % HDd;
    const float* src = (sel == 0) ? Wq : (sel == 1) ? Wk : Wv;
    dst[i] = src[((l * Hh + h) * Dd + d) * HDd + kk];
}

// ---- embedding ----
__global__ void embed_k(const int* __restrict__ idx,
                        const float* __restrict__ tok,
                        const float* __restrict__ pos) {
    int i = blockIdx.x * blockDim.x + threadIdx.x;
    if (i >= NT * Dd) return;
    int d = i % Dd;
    int n = i / Dd;
    int t = n % Tt;
    g_x[i] = tok[idx[n] * Dd + d] + pos[t * Dd + d];
}

// ---- layernorm ----
__global__ void lnorm_k(const float* __restrict__ in, float* __restrict__ out,
                        const float* __restrict__ g, const float* __restrict__ b) {
    int row = blockIdx.x;
    const float* xr = in + (size_t)row * Dd;
    __shared__ float r1[256];
    __shared__ float r2[256];
    float s = 0.f, ss = 0.f;
    for (int d = threadIdx.x; d < Dd; d += 256) {
        float v = xr[d];
        s += v; ss += v * v;
    }
    r1[threadIdx.x] = s; r2[threadIdx.x] = ss;
    __syncthreads();
    for (int o = 128; o > 0; o >>= 1) {
        if (threadIdx.x < o) { r1[threadIdx.x] += r1[threadIdx.x + o]; r2[threadIdx.x] += r2[threadIdx.x + o]; }
        __syncthreads();
    }
    float mean = r1[0] / Dd;
    float var  = r2[0] / Dd - mean * mean;
    float inv  = rsqrtf(var + 1e-5f);
    for (int d = threadIdx.x; d < Dd; d += 256) {
        out[(size_t)row * Dd + d] = (xr[d] - mean) * inv * g[d] + b[d];
    }
}

// ---- fused attention over fused-qkv layout [NT, 2160] ----
__global__ void attn_k(const float* __restrict__ qkv, float* __restrict__ ob) {
    int t = blockIdx.x, h = blockIdx.y, b = blockIdx.z;
    int tid = threadIdx.x;      // 256
    __shared__ float qr[HDd];
    __shared__ float att[Tt];
    __shared__ float red[256];

    const size_t qoff = (size_t)(b * Tt + t) * QKVW + h * HDd;
    if (tid < HDd) qr[tid] = qkv[qoff + tid];
    __syncthreads();

    const float scale = 1.0f / sqrtf((float)HDd);
    for (int s = tid; s < Tt; s += 256) {
        float dot = -1e30f;
        if (s <= t) {
            dot = 0.f;
            const float* kr = qkv + (size_t)(b * Tt + s) * QKVW + HHd + h * HDd;
            #pragma unroll
            for (int d = 0; d < HDd; d++) dot += qr[d] * kr[d];
            dot *= scale;
        }
        att[s] = dot;
    }
    __syncthreads();

    float mx = -1e30f;
    for (int s = tid; s < Tt; s += 256) mx = fmaxf(mx, att[s]);
    red[tid] = mx; __syncthreads();
    for (int o = 128; o > 0; o >>= 1) {
        if (tid < o) red[tid] = fmaxf(red[tid], red[tid + o]);
        __syncthreads();
    }
    mx = red[0];
    __syncthreads();

    float sum = 0.f;
    for (int s = tid; s < Tt; s += 256) {
        float e = __expf(att[s] - mx);
        att[s] = e; sum += e;
    }
    red[tid] = sum; __syncthreads();
    for (int o = 128; o > 0; o >>= 1) {
        if (tid < o) red[tid] += red[tid + o];
        __syncthreads();
    }
    float inv = 1.f / red[0];
    __syncthreads();

    for (int d = tid; d < HDd; d += 256) {
        float accv = 0.f;
        const float* vcol = qkv + 2 * HHd + h * HDd + d;
        for (int s = 0; s <= t; s++)
            accv += att[s] * vcol[(size_t)(b * Tt + s) * QKVW];
        ob[(size_t)(b * Tt + t) * HHd + h * HDd + d] = accv * inv;
    }
}

// ---- host ----
static float* sym_addr(const void* sym) {
    void* p = nullptr;
    cudaGetSymbolAddress(&p, sym);
    return (float*)p;
}

#define HG_SMEM (2 * BUFSZ * 2)   // 81920 bytes

static void tgemm(const float* A, const float* B, const float* bias,
                  const float* resid, float* C,
                  int M, int N, int K, int lda, int ldb, int ldc, int flags) {
    static bool attr_set = false;
    if (!attr_set) {
        cudaFuncSetAttribute(hgemm_k, cudaFuncAttributeMaxDynamicSharedMemorySize, HG_SMEM);
        attr_set = true;
    }
    dim3 g((M + 127) / 128, (N + 127) / 128);   // m fastest -> L2 reuse of B strip
    hgemm_k<<<g, 256, HG_SMEM>>>(A, B, bias, resid, C, M, N, K, lda, ldb, ldc, flags);
}

extern "C" void kernel_launch(void* const* d_in, const int* in_sizes, int n_in,
                              void* d_out, int out_size) {
    const int*   idx     = (const int*)  d_in[0];
    const float* tok_emb = (const float*)d_in[1];
    const float* pos_emb = (const float*)d_in[2];
    const float* Wq      = (const float*)d_in[3];
    const float* Wk      = (const float*)d_in[4];
    const float* Wv      = (const float*)d_in[5];
    const float* Wproj   = (const float*)d_in[6];
    const float* bproj   = (const float*)d_in[7];
    const float* ln1_g   = (const float*)d_in[8];
    const float* ln1_b   = (const float*)d_in[9];
    const float* ln2_g   = (const float*)d_in[10];
    const float* ln2_b   = (const float*)d_in[11];
    const float* W1      = (const float*)d_in[12];
    const float* b1      = (const float*)d_in[13];
    const float* W2      = (const float*)d_in[14];
    const float* b2      = (const float*)d_in[15];
    const float* lnf_g   = (const float*)d_in[16];
    const float* lnf_b   = (const float*)d_in[17];
    const float* Wlm     = (const float*)d_in[18];
    const float* blm     = (const float*)d_in[19];
    float* out = (float*)d_out;

    float* px    = sym_addr(g_x);
    float* ph    = sym_addr(g_h);
    float* pqkv  = sym_addr(g_qkv);
    float* po    = sym_addr(g_o);
    float* pff   = sym_addr(g_ff);
    float* pwqkv = sym_addr(g_wqkv);

    {
        const int total = Lx * Dd * QKVW;
        repack_qkv_k<<<(total + 255) / 256, 256>>>(Wq, Wk, Wv, pwqkv);
    }
    {
        const int total = NT * Dd;
        embed_k<<<(total + 255) / 256, 256>>>(idx, tok_emb, pos_emb);
    }

    dim3 gATT(Tt, Hh, Bbt);

    for (int l = 0; l < Lx; l++) {
        lnorm_k<<<NT, 256>>>(px, ph, ln1_g + l * Dd, ln1_b + l * Dd);
        // qkv = h @ Wqkv  -> [NT, 2160]
        tgemm(ph, pwqkv + (size_t)l * Dd * QKVW, nullptr, nullptr, pqkv,
              NT, QKVW, Dd, Dd, QKVW, QKVW, 0);
        attn_k<<<gATT, 256>>>(pqkv, po);
        // x = x + o @ Wproj + bproj
        tgemm(po, Wproj + (size_t)l * HHd * Dd, bproj + l * Dd, px, px,
              NT, Dd, HHd, HHd, Dd, Dd, F_BIAS | F_RESID);
        lnorm_k<<<NT, 256>>>(px, ph, ln2_g + l * Dd, ln2_b + l * Dd);
        // ff = relu(h @ W1 + b1)
        tgemm(ph, W1 + (size_t)l * Dd * FFf, b1 + (size_t)l * FFf, nullptr, pff,
              NT, FFf, Dd, Dd, FFf, FFf, F_BIAS | F_RELU);
        // x = x + ff @ W2 + b2
        tgemm(pff, W2 + (size_t)l * FFf * Dd, b2 + l * Dd, px, px,
              NT, Dd, FFf, FFf, Dd, Dd, F_BIAS | F_RESID);
    }

    lnorm_k<<<NT, 256>>>(px, ph, lnf_g, lnf_b);
    tgemm(ph, Wlm, blm, nullptr, out,
          NT, Vv, Dd, Dd, Vv, Vv, F_BIAS);
}

// round 5
// speedup vs baseline: 2.3315x; 1.3208x over previous
#include <cuda_runtime.h>
#include <cuda_bf16.h>
#include <stdint.h>
#include <math.h>

// ---- problem constants ----
#define Lx   12
#define Dd   726
#define Hh   16
#define HDd  45
#define Tt   258
#define Vv   50257
#define Bbt  16
#define FFf  2904           // 4*D
#define NT   (Bbt*Tt)       // 4128 tokens
#define HHd  (Hh*HDd)       // 720
#define QKVW (3*HHd)        // 2160

#define PDd  728            // Dd padded to 8
#define PVv  50264          // Vv padded to 8

#define F_BIAS  1
#define F_RELU  2
#define F_RESID 4
#define F_SPLIT 8

// ---- fp32 scratch ----
__device__ float g_x   [NT*Dd];
__device__ float g_qkv [NT*QKVW];

// ---- bf16 hi/lo planes ----
__device__ __nv_bfloat16 g_hh [NT*PDd],  g_hl [NT*PDd];     // LN output
__device__ __nv_bfloat16 g_oh [NT*HHd],  g_ol [NT*HHd];     // attn output
__device__ __nv_bfloat16 g_ffh[NT*FFf],  g_ffl[NT*FFf];     // relu(ff1)
__device__ __nv_bfloat16 g_wqkvh[Lx*Dd*QKVW], g_wqkvl[Lx*Dd*QKVW];
__device__ __nv_bfloat16 g_wph [Lx*HHd*PDd],  g_wpl [Lx*HHd*PDd];
__device__ __nv_bfloat16 g_w1h [Lx*Dd*FFf],   g_w1l [Lx*Dd*FFf];
__device__ __nv_bfloat16 g_w2h [Lx*FFf*PDd],  g_w2l [Lx*FFf*PDd];
__device__ __nv_bfloat16 g_wlmh[Dd*PVv],      g_wlml[Dd*PVv];

// =====================================================================
// helpers
// =====================================================================
__device__ __forceinline__ uint32_t smem_u32(const void* p) {
    uint32_t a;
    asm("{ .reg .u64 t; cvta.to.shared.u64 t, %1; cvt.u32.u64 %0, t; }"
        : "=r"(a) : "l"(p));
    return a;
}
__device__ __forceinline__ void ldsm4(uint32_t& r0, uint32_t& r1,
                                      uint32_t& r2, uint32_t& r3, uint32_t addr) {
    asm volatile("ldmatrix.sync.aligned.m8n8.x4.shared.b16 {%0,%1,%2,%3}, [%4];"
                 : "=r"(r0), "=r"(r1), "=r"(r2), "=r"(r3) : "r"(addr));
}
__device__ __forceinline__ void ldsm4t(uint32_t& r0, uint32_t& r1,
                                       uint32_t& r2, uint32_t& r3, uint32_t addr) {
    asm volatile("ldmatrix.sync.aligned.m8n8.x4.trans.shared.b16 {%0,%1,%2,%3}, [%4];"
                 : "=r"(r0), "=r"(r1), "=r"(r2), "=r"(r3) : "r"(addr));
}
__device__ __forceinline__ void mma16816(float* c, const uint32_t* a,
                                         uint32_t b0, uint32_t b1) {
    asm volatile(
        "mma.sync.aligned.m16n8k16.row.col.f32.bf16.bf16.f32 "
        "{%0,%1,%2,%3},{%4,%5,%6,%7},{%8,%9},{%0,%1,%2,%3};"
        : "+f"(c[0]), "+f"(c[1]), "+f"(c[2]), "+f"(c[3])
        : "r"(a[0]), "r"(a[1]), "r"(a[2]), "r"(a[3]), "r"(b0), "r"(b1));
}
__device__ __forceinline__ void cpa16(uint32_t dst, const void* src, int bytes) {
    asm volatile("cp.async.ca.shared.global [%0], [%1], 16, %2;"
                 :: "r"(dst), "l"(src), "r"(bytes));
}
__device__ __forceinline__ void cpa_commit() {
    asm volatile("cp.async.commit_group;" ::: "memory");
}
__device__ __forceinline__ void cpa_wait2() {
    asm volatile("cp.async.wait_group 2;" ::: "memory");
}
__device__ __forceinline__ void split2(float v, __nv_bfloat16& h, __nv_bfloat16& l) {
    h = __float2bfloat16(v);
    l = __float2bfloat16(v - __bfloat162float(h));
}

// =====================================================================
// GEMM: C[M,N] = A[M,K] @ B[K,N], A/B as pre-split bf16 hi/lo planes.
// A planes [M,ApK] k-major; B planes [K,BpN] n-major (ldmatrix.trans).
// CTA 128x128, K-chunk 32, 3-stage cp.async pipeline, 8 warps 4m x 2n.
// =====================================================================
#define KCH 32
#define STG 32768
#define HG_SMEM (3*STG)     // 98304

__global__ __launch_bounds__(256, 2) void hgemm_k(
    const __nv_bfloat16* __restrict__ Ah, const __nv_bfloat16* __restrict__ Al,
    const __nv_bfloat16* __restrict__ Bh, const __nv_bfloat16* __restrict__ Bl,
    const float* __restrict__ bias, const float* __restrict__ resid,
    float* __restrict__ C, __nv_bfloat16* __restrict__ Ch, __nv_bfloat16* __restrict__ Cl,
    int M, int N, int K, int ApK, int BpN, int ldc, int flags)
{
    extern __shared__ __align__(1024) char smraw[];
    const uint32_t sbase = smem_u32(smraw);

    const int tid  = threadIdx.x;
    const int wid  = tid >> 5;
    const int lane = tid & 31;
    const int warp_m = wid & 3;
    const int warp_n = wid >> 2;

    const int m0 = blockIdx.x << 7;
    const int n0 = blockIdx.y << 7;
    const int nCh = (K + KCH - 1) / KCH;

    float c[2][8][4];
    #pragma unroll
    for (int i = 0; i < 2; i++)
        #pragma unroll
        for (int j = 0; j < 8; j++)
            #pragma unroll
            for (int q = 0; q < 4; q++) c[i][j][q] = 0.f;

    // precomputed ldmatrix in-plane offsets (swizzled)
    uint32_t aoff[2][2], boff[4][2];
    #pragma unroll
    for (int mt = 0; mt < 2; mt++)
        #pragma unroll
        for (int ks = 0; ks < 2; ks++) {
            uint32_t o = (uint32_t)((warp_m * 32 + mt * 16 + (lane & 15)) * 64
                                    + ks * 32 + ((lane >> 4) << 4));
            aoff[mt][ks] = o ^ ((o >> 3) & 0x30u);
        }
    #pragma unroll
    for (int nt2 = 0; nt2 < 4; nt2++)
        #pragma unroll
        for (int ks = 0; ks < 2; ks++) {
            uint32_t o = (uint32_t)((ks * 16 + ((lane >> 3) & 1) * 8 + (lane & 7)) * 256
                                    + warp_n * 128 + nt2 * 32 + ((lane >> 4) << 4));
            boff[nt2][ks] = o ^ ((o >> 4) & 0xF0u);
        }

    auto issue = [&](int ch) {
        const uint32_t st = sbase + (uint32_t)(ch % 3) * STG;
        const int k0 = ch * KCH;
        #pragma unroll
        for (int i = 0; i < 4; i++) {
            int g = tid + (i << 8);
            int seg = g & 3, r = (g >> 2) & 127;
            bool pl = g >= 512;
            const __nv_bfloat16* src = pl ? Al : Ah;
            int m = m0 + r, k = k0 + (seg << 3);
            int bytes = (m < M && k < ApK) ? 16 : 0;
            const void* p = bytes ? (const void*)(src + (size_t)m * ApK + k)
                                  : (const void*)src;
            uint32_t o = (uint32_t)(r * 64 + (seg << 4));
            o ^= (o >> 3) & 0x30u;
            cpa16(st + (pl ? 8192u : 0u) + o, p, bytes);
        }
        #pragma unroll
        for (int i = 0; i < 4; i++) {
            int g = tid + (i << 8);
            int seg = g & 15, r = (g >> 4) & 31;
            bool pl = g >= 512;
            const __nv_bfloat16* src = pl ? Bl : Bh;
            int k = k0 + r, n = n0 + (seg << 3);
            int bytes = (k < K && n < BpN) ? 16 : 0;
            const void* p = bytes ? (const void*)(src + (size_t)k * BpN + n)
                                  : (const void*)src;
            uint32_t o = (uint32_t)(r * 256 + (seg << 4));
            o ^= (o >> 4) & 0xF0u;
            cpa16(st + 16384u + (pl ? 8192u : 0u) + o, p, bytes);
        }
    };

    // prologue: 3 stages
    #pragma unroll
    for (int s = 0; s < 3; s++) {
        if (s < nCh) issue(s);
        cpa_commit();
    }

    for (int ch = 0; ch < nCh; ch++) {
        cpa_wait2();
        __syncthreads();

        const uint32_t st = sbase + (uint32_t)(ch % 3) * STG;
        #pragma unroll
        for (int ks = 0; ks < 2; ks++) {
            uint32_t ahi[2][4], alo[2][4];
            #pragma unroll
            for (int mt = 0; mt < 2; mt++) {
                ldsm4(ahi[mt][0], ahi[mt][1], ahi[mt][2], ahi[mt][3], st + aoff[mt][ks]);
                ldsm4(alo[mt][0], alo[mt][1], alo[mt][2], alo[mt][3], st + 8192u + aoff[mt][ks]);
            }
            #pragma unroll
            for (int nt2 = 0; nt2 < 4; nt2++) {
                uint32_t bh[4], bl[4];
                ldsm4t(bh[0], bh[1], bh[2], bh[3], st + 16384u + boff[nt2][ks]);
                ldsm4t(bl[0], bl[1], bl[2], bl[3], st + 24576u + boff[nt2][ks]);
                #pragma unroll
                for (int hh = 0; hh < 2; hh++) {
                    const int nt = nt2 * 2 + hh;
                    #pragma unroll
                    for (int mt = 0; mt < 2; mt++) {
                        mma16816(c[mt][nt], ahi[mt], bh[hh * 2], bh[hh * 2 + 1]);
                        mma16816(c[mt][nt], ahi[mt], bl[hh * 2], bl[hh * 2 + 1]);
                        mma16816(c[mt][nt], alo[mt], bh[hh * 2], bh[hh * 2 + 1]);
                    }
                }
            }
        }
        __syncthreads();
        if (ch + 3 < nCh) issue(ch + 3);
        cpa_commit();
    }

    // ---- epilogue ----
    #pragma unroll
    for (int mt = 0; mt < 2; mt++) {
        #pragma unroll
        for (int nt = 0; nt < 8; nt++) {
            int rb = m0 + warp_m * 32 + mt * 16 + (lane >> 2);
            int nc = n0 + warp_n * 64 + nt * 8 + ((lane & 3) << 1);
            #pragma unroll
            for (int half = 0; half < 2; half++) {
                int m = rb + half * 8;
                if (m < M) {
                    #pragma unroll
                    for (int j = 0; j < 2; j++) {
                        int n = nc + j;
                        if (n < N) {
                            float v = c[mt][nt][half * 2 + j];
                            if (flags & F_BIAS)  v += bias[n];
                            if (flags & F_RESID) v += resid[(size_t)m * ldc + n];
                            if (flags & F_RELU)  v = fmaxf(v, 0.f);
                            if (flags & F_SPLIT) {
                                __nv_bfloat16 h, l;
                                split2(v, h, l);
                                Ch[(size_t)m * ldc + n] = h;
                                Cl[(size_t)m * ldc + n] = l;
                            } else {
                                C[(size_t)m * ldc + n] = v;
                            }
                        }
                    }
                }
            }
        }
    }
}

// =====================================================================
// weight prep kernels
// =====================================================================
// repack+split QKV: (L,H,D,HD)x3 -> planes [L][Dd rows][QKVW cols]
__global__ void repack_qkv_k(const float* __restrict__ Wq,
                             const float* __restrict__ Wk,
                             const float* __restrict__ Wv,
                             __nv_bfloat16* __restrict__ dh,
                             __nv_bfloat16* __restrict__ dl) {
    int i = blockIdx.x * blockDim.x + threadIdx.x;
    const int total = Lx * Dd * QKVW;
    if (i >= total) return;
    int j    = i % QKVW;
    int rest = i / QKVW;
    int d    = rest % Dd;
    int l    = rest / Dd;
    int sel = j / HHd;
    int n   = j % HHd;
    int h  = n / HDd;
    int kk = n % HDd;
    const float* src = (sel == 0) ? Wq : (sel == 1) ? Wk : Wv;
    float v = src[((l * Hh + h) * Dd + d) * HDd + kk];
    __nv_bfloat16 hi, lo;
    split2(v, hi, lo);
    dh[i] = hi; dl[i] = lo;
}

// generic split with column padding: src [R,C] fp32 -> [R,Cp] hi/lo
__global__ void split_pad_k(const float* __restrict__ src,
                            __nv_bfloat16* __restrict__ dh,
                            __nv_bfloat16* __restrict__ dl,
                            int R, int C, int Cp) {
    int i = blockIdx.x * blockDim.x + threadIdx.x;
    if (i >= R * Cp) return;
    int r = i / Cp, c = i % Cp;
    float v = (c < C) ? src[(size_t)r * C + c] : 0.f;
    __nv_bfloat16 hi, lo;
    split2(v, hi, lo);
    dh[i] = hi; dl[i] = lo;
}

// ---- embedding ----
__global__ void embed_k(const int* __restrict__ idx,
                        const float* __restrict__ tok,
                        const float* __restrict__ pos) {
    int i = blockIdx.x * blockDim.x + threadIdx.x;
    if (i >= NT * Dd) return;
    int d = i % Dd;
    int n = i / Dd;
    int t = n % Tt;
    g_x[i] = tok[idx[n] * Dd + d] + pos[t * Dd + d];
}

// ---- layernorm -> split planes (stride PDd, pad zero) ----
__global__ void lnorm_split_k(const float* __restrict__ in,
                              __nv_bfloat16* __restrict__ oh,
                              __nv_bfloat16* __restrict__ ol,
                              const float* __restrict__ g, const float* __restrict__ b) {
    int row = blockIdx.x;
    const float* xr = in + (size_t)row * Dd;
    __shared__ float r1[256];
    __shared__ float r2[256];
    float s = 0.f, ss = 0.f;
    for (int d = threadIdx.x; d < Dd; d += 256) {
        float v = xr[d];
        s += v; ss += v * v;
    }
    r1[threadIdx.x] = s; r2[threadIdx.x] = ss;
    __syncthreads();
    for (int o = 128; o > 0; o >>= 1) {
        if (threadIdx.x < o) { r1[threadIdx.x] += r1[threadIdx.x + o]; r2[threadIdx.x] += r2[threadIdx.x + o]; }
        __syncthreads();
    }
    float mean = r1[0] / Dd;
    float var  = r2[0] / Dd - mean * mean;
    float inv  = rsqrtf(var + 1e-5f);
    for (int d = threadIdx.x; d < PDd; d += 256) {
        float v = 0.f;
        if (d < Dd) v = (xr[d] - mean) * inv * g[d] + b[d];
        __nv_bfloat16 hi, lo;
        split2(v, hi, lo);
        oh[(size_t)row * PDd + d] = hi;
        ol[(size_t)row * PDd + d] = lo;
    }
}

// ---- fused attention: qkv fp32 [NT,2160] -> o split planes [NT,720] ----
__global__ void attn_k(const float* __restrict__ qkv,
                       __nv_bfloat16* __restrict__ oh,
                       __nv_bfloat16* __restrict__ ol) {
    int t = blockIdx.x, h = blockIdx.y, b = blockIdx.z;
    int tid = threadIdx.x;      // 256
    __shared__ float qr[HDd];
    __shared__ float att[Tt];
    __shared__ float red[256];

    const size_t qoff = (size_t)(b * Tt + t) * QKVW + h * HDd;
    if (tid < HDd) qr[tid] = qkv[qoff + tid];
    __syncthreads();

    const float scale = 1.0f / sqrtf((float)HDd);
    for (int s = tid; s < Tt; s += 256) {
        float dot = -1e30f;
        if (s <= t) {
            dot = 0.f;
            const float* kr = qkv + (size_t)(b * Tt + s) * QKVW + HHd + h * HDd;
            #pragma unroll
            for (int d = 0; d < HDd; d++) dot += qr[d] * kr[d];
            dot *= scale;
        }
        att[s] = dot;
    }
    __syncthreads();

    float mx = -1e30f;
    for (int s = tid; s < Tt; s += 256) mx = fmaxf(mx, att[s]);
    red[tid] = mx; __syncthreads();
    for (int o = 128; o > 0; o >>= 1) {
        if (tid < o) red[tid] = fmaxf(red[tid], red[tid + o]);
        __syncthreads();
    }
    mx = red[0];
    __syncthreads();

    float sum = 0.f;
    for (int s = tid; s < Tt; s += 256) {
        float e = __expf(att[s] - mx);
        att[s] = e; sum += e;
    }
    red[tid] = sum; __syncthreads();
    for (int o = 128; o > 0; o >>= 1) {
        if (tid < o) red[tid] += red[tid + o];
        __syncthreads();
    }
    float inv = 1.f / red[0];
    __syncthreads();

    for (int d = tid; d < HDd; d += 256) {
        float accv = 0.f;
        const float* vcol = qkv + 2 * HHd + h * HDd + d;
        for (int s = 0; s <= t; s++)
            accv += att[s] * vcol[(size_t)(b * Tt + s) * QKVW];
        float v = accv * inv;
        __nv_bfloat16 hi, lo;
        split2(v, hi, lo);
        oh[(size_t)(b * Tt + t) * HHd + h * HDd + d] = hi;
        ol[(size_t)(b * Tt + t) * HHd + h * HDd + d] = lo;
    }
}

// ---- host ----
template <typename T>
static T* sym_addr(const void* sym) {
    void* p = nullptr;
    cudaGetSymbolAddress(&p, sym);
    return (T*)p;
}

static void tgemm(const __nv_bfloat16* Ah, const __nv_bfloat16* Al,
                  const __nv_bfloat16* Bh, const __nv_bfloat16* Bl,
                  const float* bias, const float* resid,
                  float* C, __nv_bfloat16* Ch, __nv_bfloat16* Cl,
                  int M, int N, int K, int ApK, int BpN, int ldc, int flags) {
    static bool attr_set = false;
    if (!attr_set) {
        cudaFuncSetAttribute(hgemm_k, cudaFuncAttributeMaxDynamicSharedMemorySize, HG_SMEM);
        attr_set = true;
    }
    dim3 g((M + 127) / 128, (N + 127) / 128);
    hgemm_k<<<g, 256, HG_SMEM>>>(Ah, Al, Bh, Bl, bias, resid, C, Ch, Cl,
                                 M, N, K, ApK, BpN, ldc, flags);
}

extern "C" void kernel_launch(void* const* d_in, const int* in_sizes, int n_in,
                              void* d_out, int out_size) {
    const int*   idx     = (const int*)  d_in[0];
    const float* tok_emb = (const float*)d_in[1];
    const float* pos_emb = (const float*)d_in[2];
    const float* Wq      = (const float*)d_in[3];
    const float* Wk      = (const float*)d_in[4];
    const float* Wv      = (const float*)d_in[5];
    const float* Wproj   = (const float*)d_in[6];
    const float* bproj   = (const float*)d_in[7];
    const float* ln1_g   = (const float*)d_in[8];
    const float* ln1_b   = (const float*)d_in[9];
    const float* ln2_g   = (const float*)d_in[10];
    const float* ln2_b   = (const float*)d_in[11];
    const float* W1      = (const float*)d_in[12];
    const float* b1      = (const float*)d_in[13];
    const float* W2      = (const float*)d_in[14];
    const float* b2      = (const float*)d_in[15];
    const float* lnf_g   = (const float*)d_in[16];
    const float* lnf_b   = (const float*)d_in[17];
    const float* Wlm     = (const float*)d_in[18];
    const float* blm     = (const float*)d_in[19];
    float* out = (float*)d_out;

    float* px   = sym_addr<float>(g_x);
    float* pqkv = sym_addr<float>(g_qkv);
    __nv_bfloat16* phh  = sym_addr<__nv_bfloat16>(g_hh);
    __nv_bfloat16* phl  = sym_addr<__nv_bfloat16>(g_hl);
    __nv_bfloat16* poh  = sym_addr<__nv_bfloat16>(g_oh);
    __nv_bfloat16* pol  = sym_addr<__nv_bfloat16>(g_ol);
    __nv_bfloat16* pffh = sym_addr<__nv_bfloat16>(g_ffh);
    __nv_bfloat16* pffl = sym_addr<__nv_bfloat16>(g_ffl);
    __nv_bfloat16* pwqh = sym_addr<__nv_bfloat16>(g_wqkvh);
    __nv_bfloat16* pwql = sym_addr<__nv_bfloat16>(g_wqkvl);
    __nv_bfloat16* pwph = sym_addr<__nv_bfloat16>(g_wph);
    __nv_bfloat16* pwpl = sym_addr<__nv_bfloat16>(g_wpl);
    __nv_bfloat16* pw1h = sym_addr<__nv_bfloat16>(g_w1h);
    __nv_bfloat16* pw1l = sym_addr<__nv_bfloat16>(g_w1l);
    __nv_bfloat16* pw2h = sym_addr<__nv_bfloat16>(g_w2h);
    __nv_bfloat16* pw2l = sym_addr<__nv_bfloat16>(g_w2l);
    __nv_bfloat16* pwlh = sym_addr<__nv_bfloat16>(g_wlmh);
    __nv_bfloat16* pwll = sym_addr<__nv_bfloat16>(g_wlml);

    // ---- weight prep ----
    {
        int tot = Lx * Dd * QKVW;
        repack_qkv_k<<<(tot + 255) / 256, 256>>>(Wq, Wk, Wv, pwqh, pwql);
        tot = Lx * HHd * PDd;
        split_pad_k<<<(tot + 255) / 256, 256>>>(Wproj, pwph, pwpl, Lx * HHd, Dd, PDd);
        tot = Lx * Dd * FFf;
        split_pad_k<<<(tot + 255) / 256, 256>>>(W1, pw1h, pw1l, Lx * Dd, FFf, FFf);
        tot = Lx * FFf * PDd;
        split_pad_k<<<(tot + 255) / 256, 256>>>(W2, pw2h, pw2l, Lx * FFf, Dd, PDd);
        tot = Dd * PVv;
        split_pad_k<<<(tot + 255) / 256, 256>>>(Wlm, pwlh, pwll, Dd, Vv, PVv);
    }
    {
        const int total = NT * Dd;
        embed_k<<<(total + 255) / 256, 256>>>(idx, tok_emb, pos_emb);
    }

    dim3 gATT(Tt, Hh, Bbt);

    for (int l = 0; l < Lx; l++) {
        lnorm_split_k<<<NT, 256>>>(px, phh, phl, ln1_g + l * Dd, ln1_b + l * Dd);
        // qkv = h @ Wqkv : [NT,726] x [726,2160]
        tgemm(phh, phl, pwqh + (size_t)l * Dd * QKVW, pwql + (size_t)l * Dd * QKVW,
              nullptr, nullptr, pqkv, nullptr, nullptr,
              NT, QKVW, Dd, PDd, QKVW, QKVW, 0);
        attn_k<<<gATT, 256>>>(pqkv, poh, pol);
        // x = x + o @ Wproj + bproj : [NT,720] x [720,726]
        tgemm(poh, pol, pwph + (size_t)l * HHd * PDd, pwpl + (size_t)l * HHd * PDd,
              bproj + l * Dd, px, px, nullptr, nullptr,
              NT, Dd, HHd, HHd, PDd, Dd, F_BIAS | F_RESID);
        lnorm_split_k<<<NT, 256>>>(px, phh, phl, ln2_g + l * Dd, ln2_b + l * Dd);
        // ff = relu(h @ W1 + b1) -> split planes : [NT,726] x [726,2904]
        tgemm(phh, phl, pw1h + (size_t)l * Dd * FFf, pw1l + (size_t)l * Dd * FFf,
              b1 + (size_t)l * FFf, nullptr, nullptr, pffh, pffl,
              NT, FFf, Dd, PDd, FFf, FFf, F_BIAS | F_RELU | F_SPLIT);
        // x = x + ff @ W2 + b2 : [NT,2904] x [2904,726]
        tgemm(pffh, pffl, pw2h + (size_t)l * FFf * PDd, pw2l + (size_t)l * FFf * PDd,
              b2 + l * Dd, px, px, nullptr, nullptr,
              NT, Dd, FFf, FFf, PDd, Dd, F_BIAS | F_RESID);
    }

    lnorm_split_k<<<NT, 256>>>(px, phh, phl, lnf_g, lnf_b);
    // logits = h @ Wlm + blm : [NT,726] x [726,50257]
    tgemm(phh, phl, pwlh, pwll, blm, nullptr, out, nullptr, nullptr,
          NT, Vv, Dd, PDd, PVv, Vv, F_BIAS);
}

// round 6
// speedup vs baseline: 2.6391x; 1.1319x over previous
#include <cuda_runtime.h>
#include <cuda_fp16.h>
#include <stdint.h>
#include <math.h>

// ---- problem constants ----
#define Lx   12
#define Dd   726
#define Hh   16
#define HDd  45
#define Tt   258
#define Vv   50257
#define Bbt  16
#define FFf  2904           // 4*D
#define NT   (Bbt*Tt)       // 4128 tokens
#define HHd  (Hh*HDd)       // 720
#define QKVW (3*HHd)        // 2160

#define PDd  728            // Dd padded to 8
#define PVv  50264          // Vv padded to 8

#define F_BIAS  1
#define F_RELU  2
#define F_RESID 4
#define F_SPLIT 8

// ---- fp32 scratch ----
__device__ float g_x   [NT*Dd];
__device__ float g_qkv [NT*QKVW];

// ---- fp16 planes: activations hi+lo, weights hi only ----
__device__ __half g_hh [NT*PDd],  g_hl [NT*PDd];     // LN output
__device__ __half g_oh [NT*HHd],  g_ol [NT*HHd];     // attn output
__device__ __half g_ffh[NT*FFf],  g_ffl[NT*FFf];     // relu(ff1)
__device__ __half g_wqkv[Lx*Dd*QKVW];
__device__ __half g_wp  [Lx*HHd*PDd];
__device__ __half g_w1  [Lx*Dd*FFf];
__device__ __half g_w2  [Lx*FFf*PDd];
__device__ __half g_wlm [Dd*PVv];

// =====================================================================
// helpers
// =====================================================================
__device__ __forceinline__ uint32_t smem_u32(const void* p) {
    uint32_t a;
    asm("{ .reg .u64 t; cvta.to.shared.u64 t, %1; cvt.u32.u64 %0, t; }"
        : "=r"(a) : "l"(p));
    return a;
}
__device__ __forceinline__ void ldsm4(uint32_t& r0, uint32_t& r1,
                                      uint32_t& r2, uint32_t& r3, uint32_t addr) {
    asm volatile("ldmatrix.sync.aligned.m8n8.x4.shared.b16 {%0,%1,%2,%3}, [%4];"
                 : "=r"(r0), "=r"(r1), "=r"(r2), "=r"(r3) : "r"(addr));
}
__device__ __forceinline__ void ldsm4t(uint32_t& r0, uint32_t& r1,
                                       uint32_t& r2, uint32_t& r3, uint32_t addr) {
    asm volatile("ldmatrix.sync.aligned.m8n8.x4.trans.shared.b16 {%0,%1,%2,%3}, [%4];"
                 : "=r"(r0), "=r"(r1), "=r"(r2), "=r"(r3) : "r"(addr));
}
__device__ __forceinline__ void mma16816(float* c, const uint32_t* a,
                                         uint32_t b0, uint32_t b1) {
    asm volatile(
        "mma.sync.aligned.m16n8k16.row.col.f32.f16.f16.f32 "
        "{%0,%1,%2,%3},{%4,%5,%6,%7},{%8,%9},{%0,%1,%2,%3};"
        : "+f"(c[0]), "+f"(c[1]), "+f"(c[2]), "+f"(c[3])
        : "r"(a[0]), "r"(a[1]), "r"(a[2]), "r"(a[3]), "r"(b0), "r"(b1));
}
__device__ __forceinline__ void cpa16(uint32_t dst, const void* src, int bytes) {
    asm volatile("cp.async.ca.shared.global [%0], [%1], 16, %2;"
                 :: "r"(dst), "l"(src), "r"(bytes));
}
__device__ __forceinline__ void cpa_commit() {
    asm volatile("cp.async.commit_group;" ::: "memory");
}
__device__ __forceinline__ void cpa_wait2() {
    asm volatile("cp.async.wait_group 2;" ::: "memory");
}
__device__ __forceinline__ void split2h(float v, __half& h, __half& l) {
    h = __float2half_rn(v);
    l = __float2half_rn(v - __half2float(h));
}

// =====================================================================
// GEMM: C[M,N] = A[M,K] @ B[K,N]; A = hi+lo fp16 planes, B = fp16.
// CTA 128x128, K-chunk 32, 4-stage cp.async pipeline, 8 warps 4m x 2n.
// result = Ah*B + Al*B  (2 MMAs per slab-pair)
// =====================================================================
#define KCH 32
#define STG 24576           // Ahi 8KB | Alo 8KB | B 8KB
#define HG_SMEM (4*STG)     // 98304

__global__ __launch_bounds__(256, 2) void hgemm_k(
    const __half* __restrict__ Ah, const __half* __restrict__ Al,
    const __half* __restrict__ Bh,
    const float* __restrict__ bias, const float* __restrict__ resid,
    float* __restrict__ C, __half* __restrict__ Ch, __half* __restrict__ Cl,
    int M, int N, int K, int ApK, int BpN, int ldc, int flags)
{
    extern __shared__ __align__(1024) char smraw[];
    const uint32_t sbase = smem_u32(smraw);

    const int tid  = threadIdx.x;
    const int wid  = tid >> 5;
    const int lane = tid & 31;
    const int warp_m = wid & 3;
    const int warp_n = wid >> 2;

    const int m0 = blockIdx.x << 7;
    const int n0 = blockIdx.y << 7;
    const int nCh = (K + KCH - 1) / KCH;

    float c[2][8][4];
    #pragma unroll
    for (int i = 0; i < 2; i++)
        #pragma unroll
        for (int j = 0; j < 8; j++)
            #pragma unroll
            for (int q = 0; q < 4; q++) c[i][j][q] = 0.f;

    // ldmatrix in-plane offsets (swizzled)
    uint32_t aoff[2][2], boff[4][2];
    #pragma unroll
    for (int mt = 0; mt < 2; mt++)
        #pragma unroll
        for (int ks = 0; ks < 2; ks++) {
            uint32_t o = (uint32_t)((warp_m * 32 + mt * 16 + (lane & 15)) * 64
                                    + ks * 32 + ((lane >> 4) << 4));
            aoff[mt][ks] = o ^ ((o >> 3) & 0x30u);
        }
    #pragma unroll
    for (int nt2 = 0; nt2 < 4; nt2++)
        #pragma unroll
        for (int ks = 0; ks < 2; ks++) {
            uint32_t o = (uint32_t)((ks * 16 + ((lane >> 3) & 1) * 8 + (lane & 7)) * 256
                                    + warp_n * 128 + nt2 * 32 + ((lane >> 4) << 4));
            boff[nt2][ks] = o ^ ((o >> 4) & 0xF0u);
        }

    auto issue = [&](int ch) {
        const uint32_t st = sbase + (uint32_t)(ch & 3) * STG;
        const int k0 = ch * KCH;
        // A hi+lo: 128 rows x 4 segs of 16B
        #pragma unroll
        for (int i = 0; i < 2; i++) {
            int g = tid + (i << 8);
            int seg = g & 3, r = g >> 2;
            int m = m0 + r, k = k0 + (seg << 3);
            int bytes = (m < M && k < ApK) ? 16 : 0;
            size_t gi = (size_t)m * ApK + k;
            uint32_t o = (uint32_t)(r * 64 + (seg << 4));
            o ^= (o >> 3) & 0x30u;
            cpa16(st + o,         bytes ? (const void*)(Ah + gi) : (const void*)Ah, bytes);
            cpa16(st + 8192u + o, bytes ? (const void*)(Al + gi) : (const void*)Al, bytes);
        }
        // B: 32 rows x 16 segs of 16B
        #pragma unroll
        for (int i = 0; i < 2; i++) {
            int g = tid + (i << 8);
            int seg = g & 15, r = g >> 4;
            int k = k0 + r, n = n0 + (seg << 3);
            int bytes = (k < K && n < BpN) ? 16 : 0;
            const void* p = bytes ? (const void*)(Bh + (size_t)k * BpN + n)
                                  : (const void*)Bh;
            uint32_t o = (uint32_t)(r * 256 + (seg << 4));
            o ^= (o >> 4) & 0xF0u;
            cpa16(st + 16384u + o, p, bytes);
        }
    };

    // prologue: 3 stages in flight
    #pragma unroll
    for (int s = 0; s < 3; s++) {
        if (s < nCh) issue(s);
        cpa_commit();
    }

    for (int ch = 0; ch < nCh; ch++) {
        cpa_wait2();
        __syncthreads();

        // issue next stage early (slot (ch+3)&3 is free: read finished at ch-1)
        if (ch + 3 < nCh) issue(ch + 3);
        cpa_commit();

        const uint32_t st = sbase + (uint32_t)(ch & 3) * STG;
        #pragma unroll
        for (int ks = 0; ks < 2; ks++) {
            uint32_t ahi[2][4], alo[2][4];
            #pragma unroll
            for (int mt = 0; mt < 2; mt++) {
                ldsm4(ahi[mt][0], ahi[mt][1], ahi[mt][2], ahi[mt][3], st + aoff[mt][ks]);
                ldsm4(alo[mt][0], alo[mt][1], alo[mt][2], alo[mt][3], st + 8192u + aoff[mt][ks]);
            }
            #pragma unroll
            for (int nt2 = 0; nt2 < 4; nt2++) {
                uint32_t bh[4];
                ldsm4t(bh[0], bh[1], bh[2], bh[3], st + 16384u + boff[nt2][ks]);
                #pragma unroll
                for (int hh = 0; hh < 2; hh++) {
                    const int nt = nt2 * 2 + hh;
                    #pragma unroll
                    for (int mt = 0; mt < 2; mt++) {
                        mma16816(c[mt][nt], ahi[mt], bh[hh * 2], bh[hh * 2 + 1]);
                        mma16816(c[mt][nt], alo[mt], bh[hh * 2], bh[hh * 2 + 1]);
                    }
                }
            }
        }
        __syncthreads();
    }

    // ---- epilogue ----
    #pragma unroll
    for (int mt = 0; mt < 2; mt++) {
        #pragma unroll
        for (int nt = 0; nt < 8; nt++) {
            int rb = m0 + warp_m * 32 + mt * 16 + (lane >> 2);
            int nc = n0 + warp_n * 64 + nt * 8 + ((lane & 3) << 1);
            #pragma unroll
            for (int half = 0; half < 2; half++) {
                int m = rb + half * 8;
                if (m < M) {
                    #pragma unroll
                    for (int j = 0; j < 2; j++) {
                        int n = nc + j;
                        if (n < N) {
                            float v = c[mt][nt][half * 2 + j];
                            if (flags & F_BIAS)  v += bias[n];
                            if (flags & F_RESID) v += resid[(size_t)m * ldc + n];
                            if (flags & F_RELU)  v = fmaxf(v, 0.f);
                            if (flags & F_SPLIT) {
                                __half h, l;
                                split2h(v, h, l);
                                Ch[(size_t)m * ldc + n] = h;
                                Cl[(size_t)m * ldc + n] = l;
                            } else {
                                C[(size_t)m * ldc + n] = v;
                            }
                        }
                    }
                }
            }
        }
    }
}

// =====================================================================
// weight prep kernels (single fp16 plane)
// =====================================================================
__global__ void repack_qkv_k(const float* __restrict__ Wq,
                             const float* __restrict__ Wk,
                             const float* __restrict__ Wv,
                             __half* __restrict__ d) {
    int i = blockIdx.x * blockDim.x + threadIdx.x;
    const int total = Lx * Dd * QKVW;
    if (i >= total) return;
    int j    = i % QKVW;
    int rest = i / QKVW;
    int dd   = rest % Dd;
    int l    = rest / Dd;
    int sel = j / HHd;
    int n   = j % HHd;
    int h  = n / HDd;
    int kk = n % HDd;
    const float* src = (sel == 0) ? Wq : (sel == 1) ? Wk : Wv;
    d[i] = __float2half_rn(src[((l * Hh + h) * Dd + dd) * HDd + kk]);
}

__global__ void tohalf_pad_k(const float* __restrict__ src,
                             __half* __restrict__ d,
                             int R, int C, int Cp) {
    int i = blockIdx.x * blockDim.x + threadIdx.x;
    if (i >= R * Cp) return;
    int r = i / Cp, c = i % Cp;
    d[i] = __float2half_rn((c < C) ? src[(size_t)r * C + c] : 0.f);
}

// ---- embedding ----
__global__ void embed_k(const int* __restrict__ idx,
                        const float* __restrict__ tok,
                        const float* __restrict__ pos) {
    int i = blockIdx.x * blockDim.x + threadIdx.x;
    if (i >= NT * Dd) return;
    int d = i % Dd;
    int n = i / Dd;
    int t = n % Tt;
    g_x[i] = tok[idx[n] * Dd + d] + pos[t * Dd + d];
}

// ---- layernorm -> hi/lo planes (stride PDd, pad zero) ----
__global__ void lnorm_split_k(const float* __restrict__ in,
                              __half* __restrict__ oh,
                              __half* __restrict__ ol,
                              const float* __restrict__ g, const float* __restrict__ b) {
    int row = blockIdx.x;
    const float* xr = in + (size_t)row * Dd;
    __shared__ float r1[256];
    __shared__ float r2[256];
    float s = 0.f, ss = 0.f;
    for (int d = threadIdx.x; d < Dd; d += 256) {
        float v = xr[d];
        s += v; ss += v * v;
    }
    r1[threadIdx.x] = s; r2[threadIdx.x] = ss;
    __syncthreads();
    for (int o = 128; o > 0; o >>= 1) {
        if (threadIdx.x < o) { r1[threadIdx.x] += r1[threadIdx.x + o]; r2[threadIdx.x] += r2[threadIdx.x + o]; }
        __syncthreads();
    }
    float mean = r1[0] / Dd;
    float var  = r2[0] / Dd - mean * mean;
    float inv  = rsqrtf(var + 1e-5f);
    for (int d = threadIdx.x; d < PDd; d += 256) {
        float v = 0.f;
        if (d < Dd) v = (xr[d] - mean) * inv * g[d] + b[d];
        __half hi, lo;
        split2h(v, hi, lo);
        oh[(size_t)row * PDd + d] = hi;
        ol[(size_t)row * PDd + d] = lo;
    }
}

// ---- fused attention: qkv fp32 [NT,2160] -> o hi/lo planes [NT,720] ----
__global__ void attn_k(const float* __restrict__ qkv,
                       __half* __restrict__ oh,
                       __half* __restrict__ ol) {
    int t = blockIdx.x, h = blockIdx.y, b = blockIdx.z;
    int tid = threadIdx.x;      // 256
    __shared__ float qr[HDd];
    __shared__ float att[Tt];
    __shared__ float red[256];

    const size_t qoff = (size_t)(b * Tt + t) * QKVW + h * HDd;
    if (tid < HDd) qr[tid] = qkv[qoff + tid];
    __syncthreads();

    const float scale = 1.0f / sqrtf((float)HDd);
    for (int s = tid; s < Tt; s += 256) {
        float dot = -1e30f;
        if (s <= t) {
            dot = 0.f;
            const float* kr = qkv + (size_t)(b * Tt + s) * QKVW + HHd + h * HDd;
            #pragma unroll
            for (int d = 0; d < HDd; d++) dot += qr[d] * kr[d];
            dot *= scale;
        }
        att[s] = dot;
    }
    __syncthreads();

    float mx = -1e30f;
    for (int s = tid; s < Tt; s += 256) mx = fmaxf(mx, att[s]);
    red[tid] = mx; __syncthreads();
    for (int o = 128; o > 0; o >>= 1) {
        if (tid < o) red[tid] = fmaxf(red[tid], red[tid + o]);
        __syncthreads();
    }
    mx = red[0];
    __syncthreads();

    float sum = 0.f;
    for (int s = tid; s < Tt; s += 256) {
        float e = __expf(att[s] - mx);
        att[s] = e; sum += e;
    }
    red[tid] = sum; __syncthreads();
    for (int o = 128; o > 0; o >>= 1) {
        if (tid < o) red[tid] += red[tid + o];
        __syncthreads();
    }
    float inv = 1.f / red[0];
    __syncthreads();

    for (int d = tid; d < HDd; d += 256) {
        float accv = 0.f;
        const float* vcol = qkv + 2 * HHd + h * HDd + d;
        for (int s = 0; s <= t; s++)
            accv += att[s] * vcol[(size_t)(b * Tt + s) * QKVW];
        float v = accv * inv;
        __half hi, lo;
        split2h(v, hi, lo);
        oh[(size_t)(b * Tt + t) * HHd + h * HDd + d] = hi;
        ol[(size_t)(b * Tt + t) * HHd + h * HDd + d] = lo;
    }
}

// ---- host ----
template <typename T>
static T* sym_addr(const void* sym) {
    void* p = nullptr;
    cudaGetSymbolAddress(&p, sym);
    return (T*)p;
}

static void tgemm(const __half* Ah, const __half* Al, const __half* Bh,
                  const float* bias, const float* resid,
                  float* C, __half* Ch, __half* Cl,
                  int M, int N, int K, int ApK, int BpN, int ldc, int flags) {
    static bool attr_set = false;
    if (!attr_set) {
        cudaFuncSetAttribute(hgemm_k, cudaFuncAttributeMaxDynamicSharedMemorySize, HG_SMEM);
        attr_set = true;
    }
    dim3 g((M + 127) / 128, (N + 127) / 128);
    hgemm_k<<<g, 256, HG_SMEM>>>(Ah, Al, Bh, bias, resid, C, Ch, Cl,
                                 M, N, K, ApK, BpN, ldc, flags);
}

extern "C" void kernel_launch(void* const* d_in, const int* in_sizes, int n_in,
                              void* d_out, int out_size) {
    const int*   idx     = (const int*)  d_in[0];
    const float* tok_emb = (const float*)d_in[1];
    const float* pos_emb = (const float*)d_in[2];
    const float* Wq      = (const float*)d_in[3];
    const float* Wk      = (const float*)d_in[4];
    const float* Wv      = (const float*)d_in[5];
    const float* Wproj   = (const float*)d_in[6];
    const float* bproj   = (const float*)d_in[7];
    const float* ln1_g   = (const float*)d_in[8];
    const float* ln1_b   = (const float*)d_in[9];
    const float* ln2_g   = (const float*)d_in[10];
    const float* ln2_b   = (const float*)d_in[11];
    const float* W1      = (const float*)d_in[12];
    const float* b1      = (const float*)d_in[13];
    const float* W2      = (const float*)d_in[14];
    const float* b2      = (const float*)d_in[15];
    const float* lnf_g   = (const float*)d_in[16];
    const float* lnf_b   = (const float*)d_in[17];
    const float* Wlm     = (const float*)d_in[18];
    const float* blm     = (const float*)d_in[19];
    float* out = (float*)d_out;

    float* px   = sym_addr<float>(g_x);
    float* pqkv = sym_addr<float>(g_qkv);
    __half* phh  = sym_addr<__half>(g_hh);
    __half* phl  = sym_addr<__half>(g_hl);
    __half* poh  = sym_addr<__half>(g_oh);
    __half* pol  = sym_addr<__half>(g_ol);
    __half* pffh = sym_addr<__half>(g_ffh);
    __half* pffl = sym_addr<__half>(g_ffl);
    __half* pwq  = sym_addr<__half>(g_wqkv);
    __half* pwp  = sym_addr<__half>(g_wp);
    __half* pw1  = sym_addr<__half>(g_w1);
    __half* pw2  = sym_addr<__half>(g_w2);
    __half* pwlm = sym_addr<__half>(g_wlm);

    // ---- weight prep ----
    {
        int tot = Lx * Dd * QKVW;
        repack_qkv_k<<<(tot + 255) / 256, 256>>>(Wq, Wk, Wv, pwq);
        tot = Lx * HHd * PDd;
        tohalf_pad_k<<<(tot + 255) / 256, 256>>>(Wproj, pwp, Lx * HHd, Dd, PDd);
        tot = Lx * Dd * FFf;
        tohalf_pad_k<<<(tot + 255) / 256, 256>>>(W1, pw1, Lx * Dd, FFf, FFf);
        tot = Lx * FFf * PDd;
        tohalf_pad_k<<<(tot + 255) / 256, 256>>>(W2, pw2, Lx * FFf, Dd, PDd);
        tot = Dd * PVv;
        tohalf_pad_k<<<(tot + 255) / 256, 256>>>(Wlm, pwlm, Dd, Vv, PVv);
    }
    {
        const int total = NT * Dd;
        embed_k<<<(total + 255) / 256, 256>>>(idx, tok_emb, pos_emb);
    }

    dim3 gATT(Tt, Hh, Bbt);

    for (int l = 0; l < Lx; l++) {
        lnorm_split_k<<<NT, 256>>>(px, phh, phl, ln1_g + l * Dd, ln1_b + l * Dd);
        // qkv = h @ Wqkv : [NT,726] x [726,2160]
        tgemm(phh, phl, pwq + (size_t)l * Dd * QKVW,
              nullptr, nullptr, pqkv, nullptr, nullptr,
              NT, QKVW, Dd, PDd, QKVW, QKVW, 0);
        attn_k<<<gATT, 256>>>(pqkv, poh, pol);
        // x = x + o @ Wproj + bproj : [NT,720] x [720,726]
        tgemm(poh, pol, pwp + (size_t)l * HHd * PDd,
              bproj + l * Dd, px, px, nullptr, nullptr,
              NT, Dd, HHd, HHd, PDd, Dd, F_BIAS | F_RESID);
        lnorm_split_k<<<NT, 256>>>(px, phh, phl, ln2_g + l * Dd, ln2_b + l * Dd);
        // ff = relu(h @ W1 + b1) -> hi/lo : [NT,726] x [726,2904]
        tgemm(phh, phl, pw1 + (size_t)l * Dd * FFf,
              b1 + (size_t)l * FFf, nullptr, nullptr, pffh, pffl,
              NT, FFf, Dd, PDd, FFf, FFf, F_BIAS | F_RELU | F_SPLIT);
        // x = x + ff @ W2 + b2 : [NT,2904] x [2904,726]
        tgemm(pffh, pffl, pw2 + (size_t)l * FFf * PDd,
              b2 + l * Dd, px, px, nullptr, nullptr,
              NT, Dd, FFf, FFf, PDd, Dd, F_BIAS | F_RESID);
    }

    lnorm_split_k<<<NT, 256>>>(px, phh, phl, lnf_g, lnf_b);
    // logits = h @ Wlm + blm : [NT,726] x [726,50257]
    tgemm(phh, phl, pwlm, blm, nullptr, out, nullptr, nullptr,
          NT, Vv, Dd, PDd, PVv, Vv, F_BIAS);
}